// round 6
// baseline (speedup 1.0000x reference)
#include <cuda_runtime.h>
#include <cuda_bf16.h>
#include <cstdint>

// Embedding_78666620994160
// out[t, e] = (W[e, ids[t]] + b[e]) * sqrt(512)
// ids: [8*4096] int32, W: [512, 50257] f32 (row-major), b: [512] f32
// out: [8*4096, 512] f32
//
// v5: bucket-sort (id>>5) for L2 locality + transposed smem gather.
// Entire sort prelude fused into ONE kernel (hist -> grid barrier ->
// block-0 scan -> flag -> scatter) using monotonic epoch counters so it
// is graph-replay-safe with no resets.

#define VOCAB    50257
#define EMB      512
#define N_TOKENS (8 * 4096)
#define BUCKET_SHIFT 5
#define NBINS_PAD 2048

#define PRE_BLOCKS  128
#define PRE_THREADS 256

__device__ int  g_hist[NBINS_PAD];     // zeroed at load; scan re-zeroes each launch
__device__ int  g_offs[NBINS_PAD];     // exclusive prefix (consumed by scatter)
__device__ int2 g_sorted[N_TOKENS];    // (token, id) in bucket-sorted order

// monotonic sync state (never reset; epoch-relative comparisons)
__device__ volatile int g_bar1  = 0;   // hist-done arrivals (+PRE_BLOCKS per launch)
__device__ volatile int g_flag  = 0;   // scan-done epochs   (+1 per launch)
__device__ int          g_epoch = 0;   // completed launches (stable at launch start)

// ---------------- fused sort kernel ----------------
__global__ void __launch_bounds__(PRE_THREADS, 1)
sort_kernel(const int* __restrict__ ids)
{
    const int e0 = g_epoch;                       // stable: prior launch fully done
    const int t  = blockIdx.x * PRE_THREADS + threadIdx.x;
    const int id = __ldg(&ids[t]);

    // Phase A: histogram
    atomicAdd(&g_hist[id >> BUCKET_SHIFT], 1);
    __threadfence();
    __syncthreads();
    if (threadIdx.x == 0) atomicAdd((int*)&g_bar1, 1);

    // Phase B: block 0 waits for all hist atomics, scans bins, releases flag
    if (blockIdx.x == 0) {
        if (threadIdx.x == 0) {
            const int target = e0 * PRE_BLOCKS + PRE_BLOCKS;
            while (g_bar1 < target) __nanosleep(64);
        }
        __syncthreads();
        __threadfence();                           // acquire side

        // scan 2048 bins with 256 threads, 8 bins/thread; zero g_hist
        __shared__ int wsum[8];
        int lane = threadIdx.x & 31;
        int wid  = threadIdx.x >> 5;
        int base = threadIdx.x * 8;

        int v[8], s = 0;
        #pragma unroll
        for (int j = 0; j < 8; j++) {
            v[j] = g_hist[base + j];
            g_hist[base + j] = 0;
            s += v[j];
        }
        // warp inclusive scan of s
        int x = s;
        #pragma unroll
        for (int off = 1; off < 32; off <<= 1) {
            int y = __shfl_up_sync(0xffffffffu, x, off);
            if (lane >= off) x += y;
        }
        if (lane == 31) wsum[wid] = x;
        __syncthreads();
        if (wid == 0 && lane < 8) {
            int w = wsum[lane];
            int xw = w;
            #pragma unroll
            for (int off = 1; off < 8; off <<= 1) {
                int y = __shfl_up_sync(0x000000ffu, xw, off);
                if (lane >= off) xw += y;
            }
            wsum[lane] = xw - w;                   // exclusive warp base
        }
        __syncthreads();

        int run = wsum[wid] + (x - s);             // thread's exclusive prefix
        #pragma unroll
        for (int j = 0; j < 8; j++) {
            g_offs[base + j] = run;
            run += v[j];
        }

        __threadfence();                           // publish g_offs (+ zeroed hist)
        __syncthreads();
        if (threadIdx.x == 0) {
            atomicAdd((int*)&g_flag, 1);           // g_flag -> e0+1
            g_epoch = e0 + 1;                      // for NEXT launch only
        }
    }

    // Phase C: all blocks wait for scan, then scatter
    if (threadIdx.x == 0) {
        while (g_flag < e0 + 1) __nanosleep(64);
    }
    __syncthreads();
    __threadfence();                               // acquire side

    int pos = atomicAdd(&g_offs[id >> BUCKET_SHIFT], 1);
    __stcs(&g_sorted[pos], make_int2(t, id));
}

// ---------------- transposed gather (unchanged from v4) ----------------
// Block tile: 32 sorted tokens x 64 float4 (=256 dims). blockIdx.y picks
// which half of EMB. blockDim = (32, 16) = 512 threads.
// Phase 1: lane = token -> warp gather hits few 32B sectors (sorted ids).
// Phase 2: coalesced float4 streaming stores, token-major.
// Smem pitch 65 float4/row avoids bank conflicts in both phases.

#define TOK_PER_BLK 32
#define E4_PER_BLK  64
#define S4_PITCH    65

__global__ void __launch_bounds__(512, 4)
emb_gather_tr_kernel(const float* __restrict__ W,
                     const float* __restrict__ b,
                     float* __restrict__ out)
{
    const float SCALE = 22.62741699796952f; // sqrt(512)
    __shared__ float4 S4[TOK_PER_BLK * S4_PITCH];

    int t  = threadIdx.x;                        // 0..31 local token
    int ty = threadIdx.y;                        // 0..15
    int s  = blockIdx.x * TOK_PER_BLK + t;       // sorted position
    int e4base = blockIdx.y * E4_PER_BLK;        // global float4 offset

    int id = __ldg(&g_sorted[s]).y;

    // Phase 1: gather 4 e4-slots per thread
    #pragma unroll
    for (int i = 0; i < 4; i++) {
        int e4l = ty + 16 * i;                   // 0..63 local
        int e4g = e4base + e4l;
        float4 bv = __ldg((const float4*)b + e4g);
        const float* wp = W + (size_t)(4 * e4g) * VOCAB + id;
        float4 r;
        r.x = (__ldg(wp)                      + bv.x) * SCALE;
        r.y = (__ldg(wp + (size_t)VOCAB)      + bv.y) * SCALE;
        r.z = (__ldg(wp + (size_t)2 * VOCAB)  + bv.z) * SCALE;
        r.w = (__ldg(wp + (size_t)3 * VOCAB)  + bv.w) * SCALE;
        S4[t * S4_PITCH + e4l] = r;
    }

    __syncthreads();

    // Phase 2: token-major coalesced float4 streaming stores
    int tid  = ty * 32 + t;                      // 0..511
    int tl   = tid >> 4;                         // 0..31 local token
    int ey   = tid & 15;                         // 0..15
    int token = __ldg(&g_sorted[blockIdx.x * TOK_PER_BLK + tl]).x;
    float4* outp = (float4*)out + (size_t)token * (EMB / 4) + e4base;
    #pragma unroll
    for (int i = 0; i < 4; i++) {
        int e4l = ey + 16 * i;
        __stcs(&outp[e4l], S4[tl * S4_PITCH + e4l]);
    }
}

extern "C" void kernel_launch(void* const* d_in, const int* in_sizes, int n_in,
                              void* d_out, int out_size)
{
    const int*   ids = (const int*)d_in[0];    // [32768] int32
    const float* W   = (const float*)d_in[1];  // [512*50257]
    const float* b   = (const float*)d_in[2];  // [512]
    float*       out = (float*)d_out;          // [32768*512]

    sort_kernel<<<PRE_BLOCKS, PRE_THREADS>>>(ids);

    dim3 block(32, 16, 1);
    dim3 grid(N_TOKENS / TOK_PER_BLK, EMB / (4 * E4_PER_BLK), 1);  // 1024 x 2
    emb_gather_tr_kernel<<<grid, block>>>(W, b, out);
}